// round 6
// baseline (speedup 1.0000x reference)
#include <cuda_runtime.h>
#include <cstdint>
#include <math.h>

#define B_SZ  32
#define T_LEN 2048
#define I_DIM 128
#define H_DIM 256
#define N_TOK (B_SZ * T_LEN)   // 65536

// Scratch (device globals: allocation-free rule)
__device__ float g_xB[(size_t)N_TOK * H_DIM];   // 64 MB
__device__ float g_hs[(size_t)N_TOK * H_DIM];   // 64 MB

// ---------------------------------------------------------------------------
// helpers
// ---------------------------------------------------------------------------
__device__ __forceinline__ void fma2(unsigned long long& acc,
                                     unsigned long long a,
                                     unsigned long long b) {
    asm("fma.rn.f32x2 %0, %1, %2, %0;" : "+l"(acc) : "l"(a), "l"(b));
}
__device__ __forceinline__ float lo_f(unsigned long long u) {
    return __uint_as_float((unsigned)(u & 0xffffffffull));
}
__device__ __forceinline__ float hi_f(unsigned long long u) {
    return __uint_as_float((unsigned)(u >> 32));
}
__device__ __forceinline__ unsigned long long pack2(float l, float h) {
    return (unsigned long long)__float_as_uint(l) |
           ((unsigned long long)__float_as_uint(h) << 32);
}

// ---------------------------------------------------------------------------
// fp32 tiled GEMM (round-2 version, scalar FFMA): Y[M,N] = X[M,K] @ W[K,N]
// BM=128, BN=64, BK=16, 256 threads, 8x4 micro-tile per thread.
// ---------------------------------------------------------------------------
__global__ void __launch_bounds__(256) gemm_kernel(const float* __restrict__ X,
                                                   const float* __restrict__ W,
                                                   float* __restrict__ Y,
                                                   int M, int K, int N) {
    __shared__ float Xs[16][128];
    __shared__ float Ws[16][64];

    const int tid = threadIdx.x;
    const int m0 = blockIdx.x * 128;
    const int n0 = blockIdx.y * 64;
    const int tx = tid & 15;
    const int ty = tid >> 4;

    float acc[8][4];
#pragma unroll
    for (int r = 0; r < 8; r++)
#pragma unroll
        for (int cc = 0; cc < 4; cc++) acc[r][cc] = 0.f;

    const int lrow  = tid >> 1;
    const int lpart = (tid & 1) * 8;

    for (int kt = 0; kt < K; kt += 16) {
        const float* xp = X + (size_t)(m0 + lrow) * K + kt + lpart;
        float4 v0 = *(const float4*)(xp);
        float4 v1 = *(const float4*)(xp + 4);
        Xs[lpart + 0][lrow] = v0.x;
        Xs[lpart + 1][lrow] = v0.y;
        Xs[lpart + 2][lrow] = v0.z;
        Xs[lpart + 3][lrow] = v0.w;
        Xs[lpart + 4][lrow] = v1.x;
        Xs[lpart + 5][lrow] = v1.y;
        Xs[lpart + 6][lrow] = v1.z;
        Xs[lpart + 7][lrow] = v1.w;
        {
            const int wk = tid >> 4;
            const int wn = (tid & 15) * 4;
            float4 wv = *(const float4*)(W + (size_t)(kt + wk) * N + n0 + wn);
            *(float4*)&Ws[wk][wn] = wv;
        }
        __syncthreads();

#pragma unroll
        for (int k = 0; k < 16; k++) {
            float4 xa = *(const float4*)&Xs[k][ty * 8];
            float4 xb = *(const float4*)&Xs[k][ty * 8 + 4];
            float4 wv = *(const float4*)&Ws[k][tx * 4];
            float xr[8] = {xa.x, xa.y, xa.z, xa.w, xb.x, xb.y, xb.z, xb.w};
            float wr[4] = {wv.x, wv.y, wv.z, wv.w};
#pragma unroll
            for (int r = 0; r < 8; r++)
#pragma unroll
                for (int cc = 0; cc < 4; cc++)
                    acc[r][cc] = fmaf(xr[r], wr[cc], acc[r][cc]);
        }
        __syncthreads();
    }

#pragma unroll
    for (int r = 0; r < 8; r++) {
        float4 o = make_float4(acc[r][0], acc[r][1], acc[r][2], acc[r][3]);
        *(float4*)&Y[(size_t)(m0 + ty * 8 + r) * N + n0 + tx * 4] = o;
    }
}

// ---------------------------------------------------------------------------
// Scan kernel: one CTA per batch. 512 threads.
// Thread (g = tid>>2, c = tid&3): owns columns 2g, 2g+1; k-window
// [c*64, c*64+64). Per column: 48 A-values in registers (24 f32x2 pairs),
// 16 A-values streamed from smem (lane-indexed double2 slots).
// h double-buffered in smem, skewed +4 floats per 64-block so the 4
// c-windows start at banks {0,4,8,12}: each h LDS.128 is 1 phase.
// ---------------------------------------------------------------------------
#define HSK 272                          // 256 + 4*4 skew floats per buffer

__global__ void __launch_bounds__(512, 1) scan_kernel(const float* __restrict__ A) {
    extern __shared__ float smem[];
    float*   hbuf = smem;                        // [2][272] = 2176 B
    double2* As   = (double2*)(smem + 2 * HSK);  // [8][512] double2 = 64 KB

    const int tid  = threadIdx.x;
    const int b    = blockIdx.x;
    const int g    = tid >> 2;    // 0..127 -> cols 2g, 2g+1
    const int c    = tid & 3;     // 0..3   -> k window [64c, 64c+64)
    const int k0   = c * 64;
    const int col0 = g * 2;

    // A into registers: per col, pairs (k0+2q, k0+2q+1) for q in [0,24)
    unsigned long long a2[2][24];
#pragma unroll
    for (int cc = 0; cc < 2; cc++) {
        const float* Ac = A + (size_t)k0 * H_DIM + col0 + cc;
#pragma unroll
        for (int q = 0; q < 24; q++)
            a2[cc][q] = pack2(Ac[(size_t)(2 * q) * H_DIM],
                              Ac[(size_t)(2 * q + 1) * H_DIM]);
        // A tail (k_rel 48..63) into smem: 4 double2 per col, lane slot = tid
#pragma unroll
        for (int ph = 0; ph < 4; ph++) {
            const float* At = Ac + (size_t)(48 + 4 * ph) * H_DIM;
            double2 d;
            d.x = __longlong_as_double(pack2(At[0], At[H_DIM]));
            d.y = __longlong_as_double(pack2(At[2 * H_DIM], At[3 * H_DIM]));
            As[(cc * 4 + ph) * 512 + tid] = d;
        }
    }
    // h0 = 0
    for (int i = tid; i < 2 * HSK; i += 512) hbuf[i] = 0.f;
    __syncthreads();

    const float* xB = g_xB + (size_t)b * T_LEN * H_DIM;
    float*       hs = g_hs + (size_t)b * T_LEN * H_DIM;
    const double2* Asl = As + tid;
    const int wr_off = col0 + ((col0 >> 6) << 2);   // skewed write slot

    float2 xb_cur = make_float2(0.f, 0.f);
    if (c == 0) xb_cur = *(const float2*)(xB + col0);

    for (int s = 0; s < T_LEN; s++) {
        const int rb = s & 1;
        float2 xb_nxt = xb_cur;
        if (c == 0 && s + 1 < T_LEN)
            xb_nxt = *(const float2*)(xB + (size_t)(s + 1) * H_DIM + col0);

        // dot over the 64-k window for 2 columns
        const double2* hp = (const double2*)(hbuf + rb * HSK + c * 68);
        unsigned long long acc0 = 0ull, acc1 = 0ull;
#pragma unroll
        for (int q = 0; q < 12; q++) {
            double2 hv = hp[q];
            unsigned long long hlo = (unsigned long long)__double_as_longlong(hv.x);
            unsigned long long hhi = (unsigned long long)__double_as_longlong(hv.y);
            fma2(acc0, a2[0][2 * q], hlo);
            fma2(acc0, a2[0][2 * q + 1], hhi);
            fma2(acc1, a2[1][2 * q], hlo);
            fma2(acc1, a2[1][2 * q + 1], hhi);
        }
#pragma unroll
        for (int ph = 0; ph < 4; ph++) {
            double2 hv = hp[12 + ph];
            unsigned long long hlo = (unsigned long long)__double_as_longlong(hv.x);
            unsigned long long hhi = (unsigned long long)__double_as_longlong(hv.y);
            double2 av0 = Asl[ph * 512];
            double2 av1 = Asl[(4 + ph) * 512];
            fma2(acc0, (unsigned long long)__double_as_longlong(av0.x), hlo);
            fma2(acc0, (unsigned long long)__double_as_longlong(av0.y), hhi);
            fma2(acc1, (unsigned long long)__double_as_longlong(av1.x), hlo);
            fma2(acc1, (unsigned long long)__double_as_longlong(av1.y), hhi);
        }

        float s0 = lo_f(acc0) + hi_f(acc0);
        float s1 = lo_f(acc1) + hi_f(acc1);
        s0 += __shfl_xor_sync(0xffffffffu, s0, 1);
        s1 += __shfl_xor_sync(0xffffffffu, s1, 1);
        s0 += __shfl_xor_sync(0xffffffffu, s0, 2);
        s1 += __shfl_xor_sync(0xffffffffu, s1, 2);

        if (c == 0) {
            float2 y;
            y.x = tanhf(s0 + xb_cur.x);
            y.y = tanhf(s1 + xb_cur.y);
            *(float2*)(hbuf + (rb ^ 1) * HSK + wr_off) = y;
            *(float2*)(hs + (size_t)s * H_DIM + col0) = y;
            xb_cur = xb_nxt;
        }
        __syncthreads();
    }
}

// ---------------------------------------------------------------------------
extern "C" void kernel_launch(void* const* d_in, const int* in_sizes, int n_in,
                              void* d_out, int out_size) {
    const float* x  = (const float*)d_in[0];   // [32,2048,128]
    const float* A  = (const float*)d_in[1];   // [256,256]
    const float* Bm = (const float*)d_in[2];   // [128,256]
    const float* C  = (const float*)d_in[3];   // [256,256]
    float* out = (float*)d_out;                // [32,2048,256]

    float* xBp = nullptr;
    float* hsp = nullptr;
    cudaGetSymbolAddress((void**)&xBp, g_xB);
    cudaGetSymbolAddress((void**)&hsp, g_hs);

    const int scan_smem = 2 * HSK * 4 + 8 * 512 * 16;   // 2176 + 65536 B
    cudaFuncSetAttribute(scan_kernel,
                         cudaFuncAttributeMaxDynamicSharedMemorySize, scan_smem);

    // 1) xB = x @ Bm : [65536,128] @ [128,256]
    gemm_kernel<<<dim3(N_TOK / 128, H_DIM / 64), 256>>>(x, Bm, xBp, N_TOK, I_DIM, H_DIM);
    // 2) sequential scan over T, one CTA per batch
    scan_kernel<<<B_SZ, 512, scan_smem>>>(A);
    // 3) out = hs @ C : [65536,256] @ [256,256]
    gemm_kernel<<<dim3(N_TOK / 128, H_DIM / 64), 256>>>(hsp, C, out, N_TOK, H_DIM, H_DIM);
}

// round 8
// speedup vs baseline: 1.3661x; 1.3661x over previous
#include <cuda_runtime.h>
#include <cstdint>
#include <math.h>

#define B_SZ  32
#define T_LEN 2048
#define I_DIM 128
#define H_DIM 256
#define N_TOK (B_SZ * T_LEN)   // 65536

// Scratch (device globals: allocation-free rule)
__device__ float g_xB[(size_t)N_TOK * H_DIM];   // 64 MB
__device__ float g_hs[(size_t)N_TOK * H_DIM];   // 64 MB

// ---------------------------------------------------------------------------
// helpers
// ---------------------------------------------------------------------------
__device__ __forceinline__ uint32_t smem_u32(const void* p) {
    uint32_t a;
    asm("{ .reg .u64 t; cvta.to.shared.u64 t, %1; cvt.u32.u64 %0, t; }"
        : "=r"(a) : "l"(p));
    return a;
}
__device__ __forceinline__ void mbar_wait(uint32_t mbar, uint32_t parity) {
    asm volatile(
        "{\n\t.reg .pred P;\n\t"
        "WAITLOOP_%=:\n\t"
        "mbarrier.try_wait.parity.acquire.cta.shared::cta.b64 P, [%0], %1, 0x989680;\n\t"
        "@P bra.uni WAITDONE_%=;\n\t"
        "bra.uni WAITLOOP_%=;\n\t"
        "WAITDONE_%=:\n\t}"
        :: "r"(mbar), "r"(parity) : "memory");
}

// ---------------------------------------------------------------------------
// fp32 tiled GEMM (round-2 version, scalar FFMA): Y[M,N] = X[M,K] @ W[K,N]
// BM=128, BN=64, BK=16, 256 threads, 8x4 micro-tile per thread.
// ---------------------------------------------------------------------------
__global__ void __launch_bounds__(256) gemm_kernel(const float* __restrict__ X,
                                                   const float* __restrict__ W,
                                                   float* __restrict__ Y,
                                                   int M, int K, int N) {
    __shared__ float Xs[16][128];
    __shared__ float Ws[16][64];

    const int tid = threadIdx.x;
    const int m0 = blockIdx.x * 128;
    const int n0 = blockIdx.y * 64;
    const int tx = tid & 15;
    const int ty = tid >> 4;

    float acc[8][4];
#pragma unroll
    for (int r = 0; r < 8; r++)
#pragma unroll
        for (int cc = 0; cc < 4; cc++) acc[r][cc] = 0.f;

    const int lrow  = tid >> 1;
    const int lpart = (tid & 1) * 8;

    for (int kt = 0; kt < K; kt += 16) {
        const float* xp = X + (size_t)(m0 + lrow) * K + kt + lpart;
        float4 v0 = *(const float4*)(xp);
        float4 v1 = *(const float4*)(xp + 4);
        Xs[lpart + 0][lrow] = v0.x;
        Xs[lpart + 1][lrow] = v0.y;
        Xs[lpart + 2][lrow] = v0.z;
        Xs[lpart + 3][lrow] = v0.w;
        Xs[lpart + 4][lrow] = v1.x;
        Xs[lpart + 5][lrow] = v1.y;
        Xs[lpart + 6][lrow] = v1.z;
        Xs[lpart + 7][lrow] = v1.w;
        {
            const int wk = tid >> 4;
            const int wn = (tid & 15) * 4;
            float4 wv = *(const float4*)(W + (size_t)(kt + wk) * N + n0 + wn);
            *(float4*)&Ws[wk][wn] = wv;
        }
        __syncthreads();

#pragma unroll
        for (int k = 0; k < 16; k++) {
            float4 xa = *(const float4*)&Xs[k][ty * 8];
            float4 xb = *(const float4*)&Xs[k][ty * 8 + 4];
            float4 wv = *(const float4*)&Ws[k][tx * 4];
            float xr[8] = {xa.x, xa.y, xa.z, xa.w, xb.x, xb.y, xb.z, xb.w};
            float wr[4] = {wv.x, wv.y, wv.z, wv.w};
#pragma unroll
            for (int r = 0; r < 8; r++)
#pragma unroll
                for (int cc = 0; cc < 4; cc++)
                    acc[r][cc] = fmaf(xr[r], wr[cc], acc[r][cc]);
        }
        __syncthreads();
    }

#pragma unroll
    for (int r = 0; r < 8; r++) {
        float4 o = make_float4(acc[r][0], acc[r][1], acc[r][2], acc[r][3]);
        *(float4*)&Y[(size_t)(m0 + ty * 8 + r) * N + n0 + tx * 4] = o;
    }
}

// ---------------------------------------------------------------------------
// Scan kernel: 2-CTA cluster per batch (64 CTAs). Each CTA owns 128 output
// columns; per step it reads the FULL h (256), computes its 128 new h values,
// and sends them to the peer via cp.async.bulk.shared::cluster + mbarrier.
// Thread (g = tid>>2, c = tid&3): col = rank*128+g, k-window [64c, 64c+64).
// A slice (64 floats) fully in registers -> zero smem A traffic, scalar FFMA.
// h double-buffered, skewed +4 floats per 64-block: the 4 c-window reads per
// warp instr land on banks {+0,+4,+8,+12} -> 1 phase per LDS.128.
// ---------------------------------------------------------------------------
#define HSK 272                          // 256 + 4*4 skew floats per buffer
#define HALF_BYTES (136 * 4)             // 544 B: one CTA's skewed half

__global__ void __launch_bounds__(512, 1) __cluster_dims__(2, 1, 1)
scan_kernel(const float* __restrict__ A) {
    __shared__ __align__(16) float hbuf[2][HSK];
    __shared__ __align__(8) unsigned long long bars[2];

    const int tid = threadIdx.x;
    uint32_t rank;
    asm("mov.u32 %0, %%cluster_ctarank;" : "=r"(rank));
    const int b   = blockIdx.x >> 1;
    const int g   = tid >> 2;            // 0..127
    const int c   = tid & 3;             // 0..3
    const int col = (int)rank * 128 + g;
    const int k0  = c * 64;

    // A slice fully into registers: A[k0+k][col], k in [0,64)
    float a[64];
    {
        const float* Ac = A + (size_t)k0 * H_DIM + col;
#pragma unroll
        for (int k = 0; k < 64; k++) a[k] = Ac[(size_t)k * H_DIM];
    }

    const uint32_t bar_u32[2] = { smem_u32(&bars[0]), smem_u32(&bars[1]) };
    if (tid == 0) {
        asm volatile("mbarrier.init.shared.b64 [%0], 1;" :: "r"(bar_u32[0]) : "memory");
        asm volatile("mbarrier.init.shared.b64 [%0], 1;" :: "r"(bar_u32[1]) : "memory");
    }
    // h0 = 0 (both buffers zeroed; buffer 0 is step-0 input)
    for (int i = tid; i < 2 * HSK; i += 512) ((float*)hbuf)[i] = 0.f;
    __syncthreads();
    // cluster-wide: mbarriers + zeroed h visible before any peer traffic
    asm volatile("barrier.cluster.arrive.aligned;" ::: "memory");
    asm volatile("barrier.cluster.wait.aligned;" ::: "memory");

    // peer destination addresses (only tid 0 uses them)
    uint32_t my_src[2], peer_dst[2], peer_bar[2];
    {
        const uint32_t prank = rank ^ 1u;
#pragma unroll
        for (int i = 0; i < 2; i++) {
            uint32_t s = smem_u32(&hbuf[i][rank * 136]);
            my_src[i] = s;
            asm("mapa.shared::cluster.u32 %0, %1, %2;" : "=r"(peer_dst[i]) : "r"(s), "r"(prank));
            asm("mapa.shared::cluster.u32 %0, %1, %2;" : "=r"(peer_bar[i]) : "r"(bar_u32[i]), "r"(prank));
        }
    }

    const float* xB = g_xB + (size_t)b * T_LEN * H_DIM;
    float*       hs = g_hs + (size_t)b * T_LEN * H_DIM;
    const int wr_off = col + ((col >> 6) << 2);     // skewed slot for my col

    float xb_cur = (c == 0) ? xB[col] : 0.f;

    for (int s = 0; s < T_LEN; s++) {
        const int rb = s & 1, wb = rb ^ 1;

        if (tid == 0 && s + 1 < T_LEN)
            asm volatile("mbarrier.arrive.expect_tx.shared.b64 _, [%0], %1;"
                         :: "r"(bar_u32[wb]), "r"((uint32_t)HALF_BYTES) : "memory");

        float xb_nxt = xb_cur;
        if (c == 0 && s + 1 < T_LEN)
            xb_nxt = xB[(size_t)(s + 1) * H_DIM + col];

        // dot over this thread's 64-k window (A in regs, h from smem)
        const float4* hp = (const float4*)(&hbuf[rb][c * 68]);
        float acc0 = 0.f, acc1 = 0.f;
#pragma unroll
        for (int q = 0; q < 16; q++) {
            float4 hv = hp[q];
            acc0 = fmaf(hv.x, a[4 * q + 0], acc0);
            acc1 = fmaf(hv.y, a[4 * q + 1], acc1);
            acc0 = fmaf(hv.z, a[4 * q + 2], acc0);
            acc1 = fmaf(hv.w, a[4 * q + 3], acc1);
        }
        float sum = acc0 + acc1;
        sum += __shfl_xor_sync(0xffffffffu, sum, 1);
        sum += __shfl_xor_sync(0xffffffffu, sum, 2);

        if (c == 0) {
            float y = tanhf(sum + xb_cur);
            hbuf[wb][wr_off] = y;
            hs[(size_t)s * H_DIM + col] = y;
            xb_cur = xb_nxt;
        }
        __syncthreads();   // local half of hbuf[wb] complete

        if (s + 1 < T_LEN) {
            if (tid == 0) {
                asm volatile("fence.proxy.async.shared::cta;" ::: "memory");
                asm volatile(
                    "cp.async.bulk.shared::cluster.shared::cta.mbarrier::complete_tx::bytes "
                    "[%0], [%1], %2, [%3];"
                    :: "r"(peer_dst[wb]), "r"(my_src[wb]),
                       "r"((uint32_t)HALF_BYTES), "r"(peer_bar[wb])
                    : "memory");
            }
            // wait for peer's half of buffer wb (phase = completion count parity)
            mbar_wait(bar_u32[wb], (uint32_t)((s >> 1) & 1));
        }
    }

    // no CTA may exit while peer DSMEM traffic could be in flight
    asm volatile("barrier.cluster.arrive.aligned;" ::: "memory");
    asm volatile("barrier.cluster.wait.aligned;" ::: "memory");
}

// ---------------------------------------------------------------------------
extern "C" void kernel_launch(void* const* d_in, const int* in_sizes, int n_in,
                              void* d_out, int out_size) {
    const float* x  = (const float*)d_in[0];   // [32,2048,128]
    const float* A  = (const float*)d_in[1];   // [256,256]
    const float* Bm = (const float*)d_in[2];   // [128,256]
    const float* C  = (const float*)d_in[3];   // [256,256]
    float* out = (float*)d_out;                // [32,2048,256]

    float* xBp = nullptr;
    float* hsp = nullptr;
    cudaGetSymbolAddress((void**)&xBp, g_xB);
    cudaGetSymbolAddress((void**)&hsp, g_hs);

    // 1) xB = x @ Bm : [65536,128] @ [128,256]
    gemm_kernel<<<dim3(N_TOK / 128, H_DIM / 64), 256>>>(x, Bm, xBp, N_TOK, I_DIM, H_DIM);
    // 2) sequential scan over T: 2-CTA cluster per batch, scalar FFMA
    scan_kernel<<<B_SZ * 2, 512>>>(A);
    // 3) out = hs @ C : [65536,256] @ [256,256]
    gemm_kernel<<<dim3(N_TOK / 128, H_DIM / 64), 256>>>(hsp, C, out, N_TOK, H_DIM, H_DIM);
}